// round 10
// baseline (speedup 1.0000x reference)
#include <cuda_runtime.h>

#define D      1024
#define NCOL   20000
#define TWO_M  512
#define DM1    1023
#define BLK    128
#define NBLK   157
#define FETA   1e-5f
#define EPS    (2.0f * FETA)
#define NIT    5
#define NSEG   8
#define SEGW   20
#define BIGSM  (BLK * BLK * (int)sizeof(float))   // 65536 B (S tile)

// ---------------- device globals (no allocation allowed) ----------------
__device__ __align__(16) float g_Spart[2][(size_t)NBLK * BLK * BLK];  // K-half partials
__device__ __align__(16) float g_uh[2][2][NBLK][D];   // [slot][chain][blk][row]
__device__ __align__(16) float g_W[2][2][NSEG][D];    // [slot][chain][seg][row]
__device__ float g_pzh[2][NBLK];
__device__ float g_Wz[2][NSEG];
__device__ __align__(16) float g_y[2][NBLK * BLK];
__device__ float g_x0[D];
__device__ float g_T0, g_q0;

// ---------------- init: x0 gather, q0 = w1.x0, zero T0 ----------------
__global__ __launch_bounds__(1024) void init_kernel(const float* __restrict__ At,
                                                    const float* __restrict__ w1) {
    __shared__ float red[32];
    int tid = threadIdx.x;
    float x0 = At[(size_t)tid * NCOL];
    g_x0[tid] = x0;
    float p = w1[tid] * x0;
    #pragma unroll
    for (int o = 16; o; o >>= 1) p += __shfl_down_sync(0xffffffffu, p, o);
    if ((tid & 31) == 0) red[tid >> 5] = p;
    __syncthreads();
    if (tid < 32) {
        float q = red[tid];
        #pragma unroll
        for (int o = 16; o; o >>= 1) q += __shfl_down_sync(0xffffffffu, q, o);
        if (tid == 0) { g_q0 = q; g_T0 = 0.0f; }
    }
}

// ---------------- T0 = ||W2_init @ a_0||^2 ; grid 16 ----------------
__global__ __launch_bounds__(256) void t0_kernel(const float* __restrict__ W2) {
    int wid = threadIdx.x >> 5, lane = threadIdx.x & 31;
    float acc = 0.0f;
    #pragma unroll
    for (int rr = 0; rr < 4; rr++) {
        int m = blockIdx.x * 32 + wid * 4 + rr;
        const float* row = W2 + (size_t)m * DM1;
        float p = 0.0f;
        for (int c = lane; c < DM1; c += 32) p = fmaf(row[c], g_x0[c], p);
        #pragma unroll
        for (int o = 16; o; o >>= 1) p += __shfl_down_sync(0xffffffffu, p, o);
        if (lane == 0) acc = fmaf(p, p, acc);
    }
    if (lane == 0) atomicAdd(&g_T0, acc);
}

// ---------------- copy b into out[N..2N) ----------------
__global__ void copyb_kernel(const float* __restrict__ b, float* __restrict__ out) {
    int i = blockIdx.x * blockDim.x + threadIdx.x;
    if (i < NCOL) out[NCOL + i] = b[i];
}

// ---------------- zero iteration state (both parities) ----------------
__global__ void zero_state_kernel() {
    int idx = blockIdx.x * blockDim.x + threadIdx.x;
    int stride = gridDim.x * blockDim.x;
    float* u = &g_uh[0][0][0][0];
    for (int i = idx; i < 2 * 2 * NBLK * D; i += stride) u[i] = 0.0f;
    float* w = &g_W[0][0][0][0];
    for (int i = idx; i < 2 * 2 * NSEG * D; i += stride) w[i] = 0.0f;
    float* y = &g_y[0][0];
    for (int i = idx; i < 2 * NBLK * BLK; i += stride) y[i] = 0.0f;
    if (idx < 2 * NBLK) (&g_pzh[0][0])[idx] = 0.0f;
    if (idx < 2 * NSEG) (&g_Wz[0][0])[idx] = 0.0f;
}

// ---------------- diag Gram partials; upper triangle in 4x8 units ----------------
// grid (157,2), 288 threads. 272 units over threads 0..271; per-thread work is
// HALF of an 8x8 tile, so all 9 warps carry equal load (16 idle lanes only).
__global__ __launch_bounds__(288) void gram_kernel(const float* __restrict__ At) {
    __shared__ float sh[32][BLK];
    const int k = blockIdx.x, s = k * BLK, kh = blockIdx.y, tid = threadIdx.x;

    // decode unit tid -> (ti4, tj8): rows [4*ti4,+4), cols [8*tj8,+8), tj8 >= floor(ti4/2)
    int uu = tid, m = 0;
    while (m < 16 && uu >= 2 * (16 - m)) { uu -= 2 * (16 - m); m++; }
    const int half = (uu >= (16 - m)) ? 1 : 0;
    const int ti4 = 2 * m + half;
    const int tj8 = m + (uu - half * (16 - m));
    const bool active = (tid < 272);

    float acc[4][8];
    #pragma unroll
    for (int i = 0; i < 4; i++)
        #pragma unroll
        for (int j = 0; j < 8; j++) acc[i][j] = 0.0f;

    for (int kt = 0; kt < 16; kt++) {
        int r0 = kh * 512 + kt * 32;
        #pragma unroll
        for (int i = 0; i < 4; i++) {
            int f = tid + 288 * i;            // covers 1024 float4
            if (f < 1024) {
                int r = f >> 5;
                int c4 = (f & 31) * 4;
                float4 v = make_float4(0.f, 0.f, 0.f, 0.f);
                if (s + c4 + 3 < NCOL)
                    v = *(const float4*)(At + (size_t)(r0 + r) * NCOL + s + c4);
                *(float4*)&sh[r][c4] = v;
            }
        }
        __syncthreads();
        if (active) {
            #pragma unroll 8
            for (int r2 = 0; r2 < 32; r2++) {
                float4 a4 = *(const float4*)&sh[r2][4 * ti4];
                float4 b4 = *(const float4*)&sh[r2][8 * tj8];
                float4 b5 = *(const float4*)&sh[r2][8 * tj8 + 4];
                float av[4] = {a4.x, a4.y, a4.z, a4.w};
                float bv[8] = {b4.x, b4.y, b4.z, b4.w, b5.x, b5.y, b5.z, b5.w};
                #pragma unroll
                for (int i = 0; i < 4; i++)
                    #pragma unroll
                    for (int j = 0; j < 8; j++) acc[i][j] = fmaf(av[i], bv[j], acc[i][j]);
            }
        }
        __syncthreads();
    }
    if (active) {
        float* Sk = g_Spart[kh] + (size_t)k * BLK * BLK;
        #pragma unroll
        for (int i = 0; i < 4; i++) {
            int row = 4 * ti4 + i;
            *(float4*)&Sk[row * BLK + 8 * tj8]     = make_float4(acc[i][0], acc[i][1], acc[i][2], acc[i][3]);
            *(float4*)&Sk[row * BLK + 8 * tj8 + 4] = make_float4(acc[i][4], acc[i][5], acc[i][6], acc[i][7]);
        }
    }
}

// ---------------- one fused Jacobi sweep: 157 CTAs, all blocks parallel ----------------
// parity p: reads W[p], u[p^1], pz[p], Wz[p]; writes u[p], pz[p], W[p^1], Wz[p^1]
// first=1: y==0 state -> skip prefix-build / phase A / S-stage / local matvec
__global__ __launch_bounds__(512) void big_kernel(const float* __restrict__ At,
                                                  const float* __restrict__ b,
                                                  float* __restrict__ out,
                                                  int p, int first, int last) {
    extern __shared__ float dsm[];                 // S tile (128x128)
    __shared__ float Ucm[D], Usm[D];
    __shared__ float pAc[16][BLK], pAs[16][BLK];
    __shared__ float plc[4][BLK], pls[4][BLK];
    __shared__ float yco[BLK], yso[BLK], ycn[BLK], ysn[BLK];
    __shared__ float zz[BLK], bb[BLK], tq[BLK], pref[BLK];
    __shared__ float sPz;

    const int tid = threadIdx.x;
    const int w = tid >> 5, lane = tid & 31;
    const int k = blockIdx.x;
    const int s = k * BLK;
    const int n = (NCOL - s < BLK) ? (NCOL - s) : BLK;
    const int seg = k / SEGW;
    const int segbase = seg * SEGW;
    const int pr = p ^ 1;

    if (tid < BLK) {
        zz[tid] = (tid < n) ? At[(size_t)DM1 * NCOL + s + tid] : 0.f;
        bb[tid] = (tid < n) ? b[s + tid] : 0.f;
    }

    if (!first) {
        // ---- build exclusive-prefix coupling vectors (float4 path) ----
        {
            const int chain = tid >> 8;
            const int slot = tid & 255;
            const float4* Wp = (const float4*)&g_W[p][chain][0][0];
            const float4* up = (const float4*)&g_uh[pr][chain][0][0];
            float4 acc = make_float4(0.f, 0.f, 0.f, 0.f);
            #pragma unroll 2
            for (int s2 = 0; s2 < seg; s2++) {
                float4 v = Wp[s2 * 256 + slot];
                acc.x += v.x; acc.y += v.y; acc.z += v.z; acc.w += v.w;
            }
            #pragma unroll 4
            for (int k2 = segbase; k2 < k; k2++) {
                float4 v = up[k2 * 256 + slot];
                acc.x += v.x; acc.y += v.y; acc.z += v.z; acc.w += v.w;
            }
            float4* dst = (float4*)(chain ? Usm : Ucm);
            dst[slot] = acc;
        }
        if (tid == 0) {
            float a = 0.f;
            for (int s2 = 0; s2 < seg; s2++) a += g_Wz[p][s2];
            for (int k2 = segbase; k2 < k; k2++) a += g_pzh[pr][k2];
            sPz = a;
        }
        if (tid < BLK) {
            yco[tid] = g_y[0][k * BLK + tid];
            yso[tid] = g_y[1][k * BLK + tid];
        }
        __syncthreads();

        // ---- Phase A: coupling dots (x_i . U), direct coalesced loads ----
        {
            const int colb = lane * 4;
            float4 vcA = make_float4(0.f,0.f,0.f,0.f), vsA = make_float4(0.f,0.f,0.f,0.f);
            if (colb < n) {
                const float* Xw = At + (size_t)(w * 64) * NCOL + s + colb;
                #pragma unroll 8
                for (int r = 0; r < 64; r++) {
                    float uc = Ucm[w * 64 + r], us = Usm[w * 64 + r];
                    float4 xv = *(const float4*)(Xw + (size_t)r * NCOL);
                    vcA.x = fmaf(uc, xv.x, vcA.x); vcA.y = fmaf(uc, xv.y, vcA.y);
                    vcA.z = fmaf(uc, xv.z, vcA.z); vcA.w = fmaf(uc, xv.w, vcA.w);
                    vsA.x = fmaf(us, xv.x, vsA.x); vsA.y = fmaf(us, xv.y, vsA.y);
                    vsA.z = fmaf(us, xv.z, vsA.z); vsA.w = fmaf(us, xv.w, vsA.w);
                }
            }
            *(float4*)&pAc[w][colb] = vcA;
            *(float4*)&pAs[w][colb] = vsA;
        }

        // ---- stage local Gram S = sum of K-half partials ----
        {
            const float4* Sg0 = (const float4*)(g_Spart[0] + (size_t)k * BLK * BLK);
            const float4* Sg1 = (const float4*)(g_Spart[1] + (size_t)k * BLK * BLK);
            float4* Ss = (float4*)dsm;
            #pragma unroll
            for (int ii = 0; ii < 8; ii++) {
                float4 a = Sg0[tid + 512 * ii];
                float4 c = Sg1[tid + 512 * ii];
                Ss[tid + 512 * ii] = make_float4(a.x + c.x, a.y + c.y, a.z + c.z, a.w + c.w);
            }
        }
        if (tid < BLK) tq[tid] = zz[tid] * yco[tid];
        __syncthreads();

        // ---- local strict-lower matvecs (both chains; reads upper triangle of S) ----
        {
            const int qq = tid >> 7, i = tid & 127, jb = qq * 32;
            float lc = 0.f, ls = 0.f;
            #pragma unroll 8
            for (int j2 = 0; j2 < 32; j2++) {
                int j = jb + j2;
                if (j < i) {
                    float sv = dsm[j * BLK + i];
                    lc = fmaf(sv, yco[j], lc);
                    ls = fmaf(sv, yso[j], ls);
                }
            }
            plc[qq][i] = lc; pls[qq][i] = ls;
        }
        if (tid < 32) {          // exclusive prefix of z*yc_old
            float v0 = tq[4*tid], v1 = tq[4*tid+1], v2 = tq[4*tid+2], v3 = tq[4*tid+3];
            float i0 = v0, i1 = i0 + v1, i2 = i1 + v2, i3 = i2 + v3;
            float run = i3;
            #pragma unroll
            for (int o = 1; o < 32; o <<= 1) {
                float u2 = __shfl_up_sync(0xffffffffu, run, o);
                if ((int)tid >= o) run += u2;
            }
            float ex = run - i3;
            pref[4*tid] = ex; pref[4*tid+1] = ex + i0;
            pref[4*tid+2] = ex + i1; pref[4*tid+3] = ex + i2;
        }
        __syncthreads();
    }

    // ---- combine + Jacobi update ----
    if (tid < BLK) {
        const int i = tid;
        float cc = 0.f, cs = 0.f, lc = 0.f, ls = 0.f, zp = 0.f;
        if (!first) {
            #pragma unroll
            for (int pp = 0; pp < 16; pp++) { cc += pAc[pp][i]; cs += pAs[pp][i]; }
            lc = plc[0][i] + plc[1][i] + plc[2][i] + plc[3][i];
            ls = pls[0][i] + pls[1][i] + pls[2][i] + pls[3][i];
            zp = sPz + pref[i];
        }
        float rc = (s + i == 0) ? 1.0f : 0.0f;
        float cnew = rc - EPS * (cc + lc - zz[i] * zp);
        float rs = fmaf(2.0f * g_T0, cnew * cnew, -2.0f * bb[i]);
        if (s + i == 0) rs += 2.0f * g_q0;
        float snew = rs - EPS * (cs + ls);
        ycn[i] = cnew; ysn[i] = snew;
        g_y[0][k * BLK + i] = cnew;
        g_y[1][k * BLK + i] = snew;
        if (last && i < n) out[s + i] = fmaf(0.5f, snew, bb[i]);
        tq[i] = zz[i] * cnew;
    }
    __syncthreads();

    if (last) return;

    if (tid < 32) {           // pz block sum of z*cnew, publish + segment delta
        float v = tq[4*tid] + tq[4*tid+1] + tq[4*tid+2] + tq[4*tid+3];
        #pragma unroll
        for (int o = 16; o; o >>= 1) v += __shfl_down_sync(0xffffffffu, v, o);
        if (tid == 0) {
            float old = g_pzh[p][k];
            g_pzh[p][k] = v;
            atomicAdd(&g_Wz[pr][seg], v - old);
        }
    }

    // ---- Phase U: u = X @ ynew; pass pairs fused for MLP 8 ----
    {
        const int g8 = lane >> 3, gl = lane & 7;     // 4 groups of 8 lanes
        for (int m = 0; m < 8; m++) {
            int r0 = w * 64 + m * 8 + g8;
            int r1 = r0 + 4;
            const float* rp0 = At + (size_t)r0 * NCOL + s;
            const float* rp1 = At + (size_t)r1 * NCOL + s;
            float uc0 = 0.f, us0 = 0.f, uc1 = 0.f, us1 = 0.f;
            #pragma unroll
            for (int it = 0; it < 4; it++) {
                int col = it * 32 + gl * 4;
                if (col < n) {
                    float4 xa = *(const float4*)(rp0 + col);
                    float4 xb = *(const float4*)(rp1 + col);
                    float y0 = ycn[col], y1 = ycn[col+1], y2 = ycn[col+2], y3 = ycn[col+3];
                    float t0 = ysn[col], t1 = ysn[col+1], t2 = ysn[col+2], t3 = ysn[col+3];
                    uc0 = fmaf(xa.x,y0,fmaf(xa.y,y1,fmaf(xa.z,y2,fmaf(xa.w,y3,uc0))));
                    us0 = fmaf(xa.x,t0,fmaf(xa.y,t1,fmaf(xa.z,t2,fmaf(xa.w,t3,us0))));
                    uc1 = fmaf(xb.x,y0,fmaf(xb.y,y1,fmaf(xb.z,y2,fmaf(xb.w,y3,uc1))));
                    us1 = fmaf(xb.x,t0,fmaf(xb.y,t1,fmaf(xb.z,t2,fmaf(xb.w,t3,us1))));
                }
            }
            #pragma unroll
            for (int o = 4; o; o >>= 1) {
                uc0 += __shfl_down_sync(0xffffffffu, uc0, o, 8);
                us0 += __shfl_down_sync(0xffffffffu, us0, o, 8);
                uc1 += __shfl_down_sync(0xffffffffu, uc1, o, 8);
                us1 += __shfl_down_sync(0xffffffffu, us1, o, 8);
            }
            if (gl == 0) {
                float oc0 = g_uh[p][0][k][r0], os0 = g_uh[p][1][k][r0];
                float oc1 = g_uh[p][0][k][r1], os1 = g_uh[p][1][k][r1];
                g_uh[p][0][k][r0] = uc0; g_uh[p][1][k][r0] = us0;
                g_uh[p][0][k][r1] = uc1; g_uh[p][1][k][r1] = us1;
                atomicAdd(&g_W[pr][0][seg][r0], uc0 - oc0);
                atomicAdd(&g_W[pr][1][seg][r0], us0 - os0);
                atomicAdd(&g_W[pr][0][seg][r1], uc1 - oc1);
                atomicAdd(&g_W[pr][1][seg][r1], us1 - os1);
            }
        }
    }
}

// ---------------- launch ----------------
extern "C" void kernel_launch(void* const* d_in, const int* in_sizes, int n_in,
                              void* d_out, int out_size) {
    const float* At = (const float*)d_in[0];
    const float* b  = (const float*)d_in[1];
    const float* w1 = (const float*)d_in[2];
    const float* W2 = (const float*)d_in[3];
    float* out = (float*)d_out;

    cudaFuncSetAttribute(big_kernel, cudaFuncAttributeMaxDynamicSharedMemorySize, BIGSM);

    init_kernel<<<1, 1024>>>(At, w1);
    t0_kernel<<<16, 256>>>(W2);
    if (out_size >= 2 * NCOL)
        copyb_kernel<<<(NCOL + 255) / 256, 256>>>(b, out);
    gram_kernel<<<dim3(NBLK, 2), 288>>>(At);
    zero_state_kernel<<<160, 1024>>>();

    for (int t = 0; t < NIT; t++)
        big_kernel<<<NBLK, 512, BIGSM>>>(At, b, out, t & 1,
                                         t == 0 ? 1 : 0, t == NIT - 1 ? 1 : 0);
}

// round 11
// speedup vs baseline: 1.2021x; 1.2021x over previous
#include <cuda_runtime.h>

#define D      1024
#define NCOL   20000
#define TWO_M  512
#define DM1    1023
#define BLK    128
#define NBLK   157
#define FETA   1e-5f
#define EPS    (2.0f * FETA)
#define NIT    4
#define NSEG   8
#define SEGW   20
#define BIGSM  (BLK * BLK * (int)sizeof(float))   // 65536 B (S tile)

// ---------------- device globals (no allocation allowed) ----------------
__device__ __align__(16) float g_Spart[2][(size_t)NBLK * BLK * BLK];  // K-half partials
__device__ __align__(16) float g_uh[2][2][NBLK][D];   // [slot][chain][blk][row]
__device__ __align__(16) float g_W[2][2][NSEG][D];    // [slot][chain][seg][row]
__device__ float g_pzh[2][NBLK];
__device__ float g_Wz[2][NSEG];
__device__ __align__(16) float g_y[2][NBLK * BLK];
__device__ float g_x0[D];
__device__ float g_T0, g_q0;

// ---------------- init: x0 gather, q0 = w1.x0, zero T0 ----------------
__global__ __launch_bounds__(1024) void init_kernel(const float* __restrict__ At,
                                                    const float* __restrict__ w1) {
    __shared__ float red[32];
    int tid = threadIdx.x;
    float x0 = At[(size_t)tid * NCOL];
    g_x0[tid] = x0;
    float p = w1[tid] * x0;
    #pragma unroll
    for (int o = 16; o; o >>= 1) p += __shfl_down_sync(0xffffffffu, p, o);
    if ((tid & 31) == 0) red[tid >> 5] = p;
    __syncthreads();
    if (tid < 32) {
        float q = red[tid];
        #pragma unroll
        for (int o = 16; o; o >>= 1) q += __shfl_down_sync(0xffffffffu, q, o);
        if (tid == 0) { g_q0 = q; g_T0 = 0.0f; }
    }
}

// ---------------- T0 = ||W2_init @ a_0||^2 ; grid 16 ----------------
__global__ __launch_bounds__(256) void t0_kernel(const float* __restrict__ W2) {
    int wid = threadIdx.x >> 5, lane = threadIdx.x & 31;
    float acc = 0.0f;
    #pragma unroll
    for (int rr = 0; rr < 4; rr++) {
        int m = blockIdx.x * 32 + wid * 4 + rr;
        const float* row = W2 + (size_t)m * DM1;
        float p = 0.0f;
        for (int c = lane; c < DM1; c += 32) p = fmaf(row[c], g_x0[c], p);
        #pragma unroll
        for (int o = 16; o; o >>= 1) p += __shfl_down_sync(0xffffffffu, p, o);
        if (lane == 0) acc = fmaf(p, p, acc);
    }
    if (lane == 0) atomicAdd(&g_T0, acc);
}

// ---------------- copy b into out[N..2N) ----------------
__global__ void copyb_kernel(const float* __restrict__ b, float* __restrict__ out) {
    int i = blockIdx.x * blockDim.x + threadIdx.x;
    if (i < NCOL) out[NCOL + i] = b[i];
}

// ---------------- zero iteration state (both parities) ----------------
__global__ void zero_state_kernel() {
    int idx = blockIdx.x * blockDim.x + threadIdx.x;
    int stride = gridDim.x * blockDim.x;
    float* u = &g_uh[0][0][0][0];
    for (int i = idx; i < 2 * 2 * NBLK * D; i += stride) u[i] = 0.0f;
    float* w = &g_W[0][0][0][0];
    for (int i = idx; i < 2 * 2 * NSEG * D; i += stride) w[i] = 0.0f;
    float* y = &g_y[0][0];
    for (int i = idx; i < 2 * NBLK * BLK; i += stride) y[i] = 0.0f;
    if (idx < 2 * NBLK) (&g_pzh[0][0])[idx] = 0.0f;
    if (idx < 2 * NSEG) (&g_Wz[0][0])[idx] = 0.0f;
}

// ---------------- diag Gram partials; grid (157,2), 256 thr, 8x8 tiles ----------------
// Measured-best (R5/R8): at the fp32 FMA roofline (~156 us). Do not "improve".
__global__ __launch_bounds__(256) void gram_kernel(const float* __restrict__ At) {
    __shared__ float sh[32][BLK];
    int k = blockIdx.x, s = k * BLK, kh = blockIdx.y, tid = threadIdx.x;
    int ty = tid >> 4, tx = tid & 15;
    float acc[8][8];
    #pragma unroll
    for (int i = 0; i < 8; i++)
        #pragma unroll
        for (int j = 0; j < 8; j++) acc[i][j] = 0.0f;

    for (int kt = 0; kt < 16; kt++) {
        int r0 = kh * 512 + kt * 32;
        #pragma unroll
        for (int i = 0; i < 4; i++) {
            int f = tid + 256 * i;
            int r = f >> 5;
            int c4 = (f & 31) * 4;
            float4 v = make_float4(0.f, 0.f, 0.f, 0.f);
            if (s + c4 + 3 < NCOL)
                v = *(const float4*)(At + (size_t)(r0 + r) * NCOL + s + c4);
            *(float4*)&sh[r][c4] = v;
        }
        __syncthreads();
        #pragma unroll 4
        for (int r2 = 0; r2 < 32; r2++) {
            float4 a4 = *(const float4*)&sh[r2][8 * ty];
            float4 a5 = *(const float4*)&sh[r2][8 * ty + 4];
            float4 b4 = *(const float4*)&sh[r2][8 * tx];
            float4 b5 = *(const float4*)&sh[r2][8 * tx + 4];
            float av[8] = {a4.x,a4.y,a4.z,a4.w,a5.x,a5.y,a5.z,a5.w};
            float bv[8] = {b4.x,b4.y,b4.z,b4.w,b5.x,b5.y,b5.z,b5.w};
            #pragma unroll
            for (int i = 0; i < 8; i++)
                #pragma unroll
                for (int j = 0; j < 8; j++) acc[i][j] = fmaf(av[i], bv[j], acc[i][j]);
        }
        __syncthreads();
    }
    float* Sk = g_Spart[kh] + (size_t)k * BLK * BLK;
    #pragma unroll
    for (int i = 0; i < 8; i++)
        #pragma unroll
        for (int j = 0; j < 8; j++)
            Sk[(8 * ty + i) * BLK + (8 * tx + j)] = acc[i][j];
}

// ---------------- one fused Jacobi sweep: 157 CTAs, all blocks parallel ----------------
// parity p: reads W[p], u[p^1], pz[p], Wz[p]; writes u[p], pz[p], W[p^1], Wz[p^1]
// first=1: y==0 state -> skip prefix-build / phase A / S-stage / local matvec
__global__ __launch_bounds__(512) void big_kernel(const float* __restrict__ At,
                                                  const float* __restrict__ b,
                                                  float* __restrict__ out,
                                                  int p, int first, int last) {
    extern __shared__ float dsm[];                 // S tile (128x128)
    __shared__ float Ucm[D], Usm[D];
    __shared__ float pAc[16][BLK], pAs[16][BLK];
    __shared__ float plc[4][BLK], pls[4][BLK];
    __shared__ float yco[BLK], yso[BLK], ycn[BLK], ysn[BLK];
    __shared__ float zz[BLK], bb[BLK], tq[BLK], pref[BLK];
    __shared__ float sPz;

    const int tid = threadIdx.x;
    const int w = tid >> 5, lane = tid & 31;
    const int k = blockIdx.x;
    const int s = k * BLK;
    const int n = (NCOL - s < BLK) ? (NCOL - s) : BLK;
    const int seg = k / SEGW;
    const int segbase = seg * SEGW;
    const int pr = p ^ 1;

    if (tid < BLK) {
        zz[tid] = (tid < n) ? At[(size_t)DM1 * NCOL + s + tid] : 0.f;
        bb[tid] = (tid < n) ? b[s + tid] : 0.f;
    }

    if (!first) {
        // ---- build exclusive-prefix coupling vectors (float4 path) ----
        {
            const int chain = tid >> 8;
            const int slot = tid & 255;
            const float4* Wp = (const float4*)&g_W[p][chain][0][0];
            const float4* up = (const float4*)&g_uh[pr][chain][0][0];
            float4 acc = make_float4(0.f, 0.f, 0.f, 0.f);
            #pragma unroll 2
            for (int s2 = 0; s2 < seg; s2++) {
                float4 v = Wp[s2 * 256 + slot];
                acc.x += v.x; acc.y += v.y; acc.z += v.z; acc.w += v.w;
            }
            #pragma unroll 4
            for (int k2 = segbase; k2 < k; k2++) {
                float4 v = up[k2 * 256 + slot];
                acc.x += v.x; acc.y += v.y; acc.z += v.z; acc.w += v.w;
            }
            float4* dst = (float4*)(chain ? Usm : Ucm);
            dst[slot] = acc;
        }
        if (tid == 0) {
            float a = 0.f;
            for (int s2 = 0; s2 < seg; s2++) a += g_Wz[p][s2];
            for (int k2 = segbase; k2 < k; k2++) a += g_pzh[pr][k2];
            sPz = a;
        }
        if (tid < BLK) {
            yco[tid] = g_y[0][k * BLK + tid];
            yso[tid] = g_y[1][k * BLK + tid];
        }
        __syncthreads();

        // ---- Phase A: coupling dots (x_i . U), direct coalesced loads ----
        {
            const int colb = lane * 4;
            float4 vcA = make_float4(0.f,0.f,0.f,0.f), vsA = make_float4(0.f,0.f,0.f,0.f);
            if (colb < n) {
                const float* Xw = At + (size_t)(w * 64) * NCOL + s + colb;
                #pragma unroll 8
                for (int r = 0; r < 64; r++) {
                    float uc = Ucm[w * 64 + r], us = Usm[w * 64 + r];
                    float4 xv = *(const float4*)(Xw + (size_t)r * NCOL);
                    vcA.x = fmaf(uc, xv.x, vcA.x); vcA.y = fmaf(uc, xv.y, vcA.y);
                    vcA.z = fmaf(uc, xv.z, vcA.z); vcA.w = fmaf(uc, xv.w, vcA.w);
                    vsA.x = fmaf(us, xv.x, vsA.x); vsA.y = fmaf(us, xv.y, vsA.y);
                    vsA.z = fmaf(us, xv.z, vsA.z); vsA.w = fmaf(us, xv.w, vsA.w);
                }
            }
            *(float4*)&pAc[w][colb] = vcA;
            *(float4*)&pAs[w][colb] = vsA;
        }

        // ---- stage local Gram S = sum of K-half partials ----
        {
            const float4* Sg0 = (const float4*)(g_Spart[0] + (size_t)k * BLK * BLK);
            const float4* Sg1 = (const float4*)(g_Spart[1] + (size_t)k * BLK * BLK);
            float4* Ss = (float4*)dsm;
            #pragma unroll
            for (int ii = 0; ii < 8; ii++) {
                float4 a = Sg0[tid + 512 * ii];
                float4 c = Sg1[tid + 512 * ii];
                Ss[tid + 512 * ii] = make_float4(a.x + c.x, a.y + c.y, a.z + c.z, a.w + c.w);
            }
        }
        if (tid < BLK) tq[tid] = zz[tid] * yco[tid];
        __syncthreads();

        // ---- local strict-lower matvecs (both chains) ----
        {
            const int qq = tid >> 7, i = tid & 127, jb = qq * 32;
            float lc = 0.f, ls = 0.f;
            #pragma unroll 8
            for (int j2 = 0; j2 < 32; j2++) {
                int j = jb + j2;
                if (j < i) {
                    float sv = dsm[j * BLK + i];
                    lc = fmaf(sv, yco[j], lc);
                    ls = fmaf(sv, yso[j], ls);
                }
            }
            plc[qq][i] = lc; pls[qq][i] = ls;
        }
        if (tid < 32) {          // exclusive prefix of z*yc_old
            float v0 = tq[4*tid], v1 = tq[4*tid+1], v2 = tq[4*tid+2], v3 = tq[4*tid+3];
            float i0 = v0, i1 = i0 + v1, i2 = i1 + v2, i3 = i2 + v3;
            float run = i3;
            #pragma unroll
            for (int o = 1; o < 32; o <<= 1) {
                float u2 = __shfl_up_sync(0xffffffffu, run, o);
                if ((int)tid >= o) run += u2;
            }
            float ex = run - i3;
            pref[4*tid] = ex; pref[4*tid+1] = ex + i0;
            pref[4*tid+2] = ex + i1; pref[4*tid+3] = ex + i2;
        }
        __syncthreads();
    }

    // ---- combine + Jacobi update ----
    if (tid < BLK) {
        const int i = tid;
        float cc = 0.f, cs = 0.f, lc = 0.f, ls = 0.f, zp = 0.f;
        if (!first) {
            #pragma unroll
            for (int pp = 0; pp < 16; pp++) { cc += pAc[pp][i]; cs += pAs[pp][i]; }
            lc = plc[0][i] + plc[1][i] + plc[2][i] + plc[3][i];
            ls = pls[0][i] + pls[1][i] + pls[2][i] + pls[3][i];
            zp = sPz + pref[i];
        }
        float rc = (s + i == 0) ? 1.0f : 0.0f;
        float cnew = rc - EPS * (cc + lc - zz[i] * zp);
        float rs = fmaf(2.0f * g_T0, cnew * cnew, -2.0f * bb[i]);
        if (s + i == 0) rs += 2.0f * g_q0;
        float snew = rs - EPS * (cs + ls);
        ycn[i] = cnew; ysn[i] = snew;
        g_y[0][k * BLK + i] = cnew;
        g_y[1][k * BLK + i] = snew;
        if (last && i < n) out[s + i] = fmaf(0.5f, snew, bb[i]);
        tq[i] = zz[i] * cnew;
    }
    __syncthreads();

    if (last) return;

    if (tid < 32) {           // pz block sum of z*cnew, publish + segment delta
        float v = tq[4*tid] + tq[4*tid+1] + tq[4*tid+2] + tq[4*tid+3];
        #pragma unroll
        for (int o = 16; o; o >>= 1) v += __shfl_down_sync(0xffffffffu, v, o);
        if (tid == 0) {
            float old = g_pzh[p][k];
            g_pzh[p][k] = v;
            atomicAdd(&g_Wz[pr][seg], v - old);
        }
    }

    // ---- Phase U: u = X @ ynew; pass pairs fused for MLP 8 ----
    {
        const int g8 = lane >> 3, gl = lane & 7;     // 4 groups of 8 lanes
        for (int m = 0; m < 8; m++) {
            int r0 = w * 64 + m * 8 + g8;
            int r1 = r0 + 4;
            const float* rp0 = At + (size_t)r0 * NCOL + s;
            const float* rp1 = At + (size_t)r1 * NCOL + s;
            float uc0 = 0.f, us0 = 0.f, uc1 = 0.f, us1 = 0.f;
            #pragma unroll
            for (int it = 0; it < 4; it++) {
                int col = it * 32 + gl * 4;
                if (col < n) {
                    float4 xa = *(const float4*)(rp0 + col);
                    float4 xb = *(const float4*)(rp1 + col);
                    float y0 = ycn[col], y1 = ycn[col+1], y2 = ycn[col+2], y3 = ycn[col+3];
                    float t0 = ysn[col], t1 = ysn[col+1], t2 = ysn[col+2], t3 = ysn[col+3];
                    uc0 = fmaf(xa.x,y0,fmaf(xa.y,y1,fmaf(xa.z,y2,fmaf(xa.w,y3,uc0))));
                    us0 = fmaf(xa.x,t0,fmaf(xa.y,t1,fmaf(xa.z,t2,fmaf(xa.w,t3,us0))));
                    uc1 = fmaf(xb.x,y0,fmaf(xb.y,y1,fmaf(xb.z,y2,fmaf(xb.w,y3,uc1))));
                    us1 = fmaf(xb.x,t0,fmaf(xb.y,t1,fmaf(xb.z,t2,fmaf(xb.w,t3,us1))));
                }
            }
            #pragma unroll
            for (int o = 4; o; o >>= 1) {
                uc0 += __shfl_down_sync(0xffffffffu, uc0, o, 8);
                us0 += __shfl_down_sync(0xffffffffu, us0, o, 8);
                uc1 += __shfl_down_sync(0xffffffffu, uc1, o, 8);
                us1 += __shfl_down_sync(0xffffffffu, us1, o, 8);
            }
            if (gl == 0) {
                float oc0 = g_uh[p][0][k][r0], os0 = g_uh[p][1][k][r0];
                float oc1 = g_uh[p][0][k][r1], os1 = g_uh[p][1][k][r1];
                g_uh[p][0][k][r0] = uc0; g_uh[p][1][k][r0] = us0;
                g_uh[p][0][k][r1] = uc1; g_uh[p][1][k][r1] = us1;
                atomicAdd(&g_W[pr][0][seg][r0], uc0 - oc0);
                atomicAdd(&g_W[pr][1][seg][r0], us0 - os0);
                atomicAdd(&g_W[pr][0][seg][r1], uc1 - oc1);
                atomicAdd(&g_W[pr][1][seg][r1], us1 - os1);
            }
        }
    }
}

// ---------------- launch ----------------
extern "C" void kernel_launch(void* const* d_in, const int* in_sizes, int n_in,
                              void* d_out, int out_size) {
    const float* At = (const float*)d_in[0];
    const float* b  = (const float*)d_in[1];
    const float* w1 = (const float*)d_in[2];
    const float* W2 = (const float*)d_in[3];
    float* out = (float*)d_out;

    cudaFuncSetAttribute(big_kernel, cudaFuncAttributeMaxDynamicSharedMemorySize, BIGSM);

    init_kernel<<<1, 1024>>>(At, w1);
    t0_kernel<<<16, 256>>>(W2);
    if (out_size >= 2 * NCOL)
        copyb_kernel<<<(NCOL + 255) / 256, 256>>>(b, out);
    gram_kernel<<<dim3(NBLK, 2), 256>>>(At);
    zero_state_kernel<<<160, 1024>>>();

    for (int t = 0; t < NIT; t++)
        big_kernel<<<NBLK, 512, BIGSM>>>(At, b, out, t & 1,
                                         t == 0 ? 1 : 0, t == NIT - 1 ? 1 : 0);
}